// round 11
// baseline (speedup 1.0000x reference)
#include <cuda_runtime.h>
#include <math.h>
#include <float.h>

#define OUTD    12
#define N_VOX   1728              // 12*12*12
#define N_ROIS  128
#define N_PTS   160000
#define NCH     64
#define NRV     (N_ROIS * N_VOX)  // 221184
#define NF4     (NRV * NCH / 4)   // 3,538,944 float4s in output

#define DEC_BLOCKS 888
#define DEC_WARPS  (DEC_BLOCKS * 8)

static_assert(N_PTS % 256 == 0, "exact build grid");

// Scratch (__device__ globals = sanctioned scratch; zero-initialized at load).
// Invariants restored every replay: d_acc + d_count re-zeroed per queue entry
// by decode; d_qn/d_done reset by last decode block out.
__device__ unsigned int d_acc[NRV * NCH];   // enc-space max accumulator (56.6MB)
__device__ int d_count[NRV];                // first-inserter detection only
__device__ int d_qn;
__device__ int d_done;
__device__ int d_queue[NRV];

// Monotonic float<->uint order-preserving encoding.
// enc: f<0 -> ~bits, else bits|0x80000000.  0x00000000 < enc(f) for ALL f,
// so zero-initialized d_acc needs no init pass (zero = identity for max).
__device__ __forceinline__ unsigned int enc_f(float f) {
    unsigned int u = __float_as_uint(f);
    return (u & 0x80000000u) ? ~u : (u | 0x80000000u);
}
__device__ __forceinline__ float dec_f(unsigned int e) {
    return (e & 0x80000000u) ? __uint_as_float(e & 0x7FFFFFFFu)
                             : __uint_as_float(~e);
}

// ---------------------------------------------------------------------------
// Kernel 1: merged zero-fill + build + SCATTER-MAX.
// Zero-fill of out (fire-and-forget STG.128) drains under the ROI loop.
// On each (point, roi) hit: 64 fire-and-forget REDG.MAX into the compact
// enc-space accumulator — no lists, no gather chain, no KMAX cap.
// ---------------------------------------------------------------------------
__global__ __launch_bounds__(256) void build_scatter_kernel(
    const float* __restrict__ rois, const float* __restrict__ pts,
    const float* __restrict__ feat, float* __restrict__ out)
{
    __shared__ float4 sA[N_ROIS];  // {cx, cy, r2_margin, cz}
    __shared__ float4 sB[N_ROIS];  // {cosa, sina, hdx, hdy}
    __shared__ float4 sC[N_ROIS];  // {hdz, vx, vy, vz}

    int t = threadIdx.x;
    int p = blockIdx.x * blockDim.x + t;      // always < N_PTS (exact grid)

    float px = pts[3 * p + 0];
    float py = pts[3 * p + 1];
    float pz = pts[3 * p + 2];

    if (t < N_ROIS) {
        const float* R = rois + t * 7;
        float cx = R[0], cy = R[1], cz = R[2];
        float dx = R[3], dy = R[4], dz = R[5];
        float ry = R[6];
        float hdx = dx * 0.5f, hdy = dy * 0.5f, hdz = dz * 0.5f;
        float r2  = (hdx * hdx + hdy * hdy) * 1.0002f + 1e-6f;  // conservative
        float ca  = cosf(-ry), sa = sinf(-ry);
        sA[t] = make_float4(cx, cy, r2, cz);
        sB[t] = make_float4(ca, sa, hdx, hdy);
        sC[t] = make_float4(hdz, dx / (float)OUTD, dy / (float)OUTD, dz / (float)OUTD);
    }

    // Zero-fill whole output: ~22 coalesced fire-and-forget STG.128/thread.
    // Writes OUT only; scatter below writes d_acc -> no ordering hazard.
    {
        float4 z = make_float4(0.f, 0.f, 0.f, 0.f);
        float4* o4 = (float4*)out;
        for (int i = p; i < NF4; i += N_PTS) __stcs(&o4[i], z);
    }
    __syncthreads();

    #pragma unroll 4
    for (int r = 0; r < N_ROIS; r++) {
        float4 A = sA[r];                     // broadcast LDS.128 (uniform r)
        float sx = px - A.x;
        float sy = py - A.y;
        float d2 = sx * sx + sy * sy;
        if (d2 > A.z) continue;               // ~99.8% rejected here

        float sz = pz - A.w;
        float4 B = sB[r];
        float4 C = sC[r];
        float lx = sx * B.x - sy * B.y;       // rotate into roi frame (angle = -ry)
        float ly = sx * B.y + sy * B.x;
        bool in_box = (lx > -B.z) && (lx < B.z) &&
                      (ly > -B.w) && (ly < B.w) &&
                      (fabsf(sz - C.x) <= C.x);
        if (!in_box) continue;

        int xi = min(OUTD - 1, max(0, (int)floorf((lx + B.z) / C.y)));
        int yi = min(OUTD - 1, max(0, (int)floorf((ly + B.w) / C.z)));
        int zi = min(OUTD - 1, max(0, (int)floorf(sz / C.w)));
        int rv = r * N_VOX + xi * (OUTD * OUTD) + yi * OUTD + zi;

        int c = atomicAdd(&d_count[rv], 1);
        if (c == 0) {                         // unique first inserter
            int qi = atomicAdd(&d_qn, 1);
            d_queue[qi] = rv;
        }

        // Scatter-max: load feature row (256B) once, fire 64 no-return
        // REDG.MAX into the compact accumulator. Zero state = identity.
        const float4* f4 = (const float4*)(feat + (size_t)p * NCH);
        unsigned int* acc = &d_acc[(size_t)rv * NCH];
        #pragma unroll
        for (int k = 0; k < NCH / 4; k++) {
            float4 v = f4[k];
            atomicMax(&acc[4 * k + 0], enc_f(v.x));
            atomicMax(&acc[4 * k + 1], enc_f(v.y));
            atomicMax(&acc[4 * k + 2], enc_f(v.z));
            atomicMax(&acc[4 * k + 3], enc_f(v.w));
        }
    }
}

// ---------------------------------------------------------------------------
// Kernel 2: decode. Warps grid-stride the ~14K queue entries. Per entry:
// read 256B of enc-space accumulator (coalesced across the warp), decode,
// write 256B to out, re-zero the accumulator + count (restores load-time
// invariant for the next replay). 2-deep pipeline on the acc loads.
// Last block out resets d_qn/d_done (ticket counter, race-free).
// ---------------------------------------------------------------------------
__global__ __launch_bounds__(256, 6) void decode_kernel(float* __restrict__ out)
{
    int lane  = threadIdx.x & 31;
    int gwarp = blockIdx.x * 8 + (threadIdx.x >> 5);
    int qn    = d_qn;                          // uniform read

    int i = gwarp;
    int nRv = -1;
    uint2 nE = make_uint2(0u, 0u);
    if (i < qn) {
        nRv = d_queue[i];
        nE  = ((const uint2*)&d_acc[(size_t)nRv * NCH])[lane];   // 256B/warp
    }
    while (nRv >= 0) {
        int rv = nRv;
        uint2 e = nE;
        i += DEC_WARPS;
        if (i < qn) {
            nRv = d_queue[i];
            nE  = ((const uint2*)&d_acc[(size_t)nRv * NCH])[lane];  // prefetch
        } else {
            nRv = -1;
        }

        // Decode and write output; re-zero accumulator + count.
        float2 v = make_float2(dec_f(e.x), dec_f(e.y));
        __stcs(&((float2*)(out + (size_t)rv * NCH))[lane], v);
        ((uint2*)&d_acc[(size_t)rv * NCH])[lane] = make_uint2(0u, 0u);
        if (lane == 0) d_count[rv] = 0;
    }

    __syncthreads();
    if (threadIdx.x == 0) {
        __threadfence();
        int ticket = atomicAdd(&d_done, 1);
        if (ticket == DEC_BLOCKS - 1) {
            d_qn = 0;
            d_done = 0;
        }
    }
}

// ---------------------------------------------------------------------------
extern "C" void kernel_launch(void* const* d_in, const int* in_sizes, int n_in,
                              void* d_out, int out_size)
{
    const float* rois = (const float*)d_in[0];       // (128, 7)
    const float* pts  = (const float*)d_in[1];       // (160000, 3)
    const float* feat = (const float*)d_in[2];       // (160000, 64)
    float* out = (float*)d_out;                      // (128, 12, 12, 12, 64)

    build_scatter_kernel<<<N_PTS / 256, 256>>>(rois, pts, feat, out);
    decode_kernel<<<DEC_BLOCKS, 256>>>(out);
}

// round 12
// speedup vs baseline: 1.7524x; 1.7524x over previous
#include <cuda_runtime.h>
#include <math.h>
#include <float.h>

#define OUTD    12
#define N_VOX   1728              // 12*12*12
#define N_ROIS  128
#define N_PTS   160000
#define NCH     64
#define KMAX    64                // cap on points per (roi,voxel); fallback handles overflow
#define NRV     (N_ROIS * N_VOX)  // 221184 = 864 * 256
#define NF4     (NRV * NCH / 4)   // 3,538,944 float4s in output

static_assert(N_PTS % 256 == 0, "exact build grid");
static_assert(NRV % 256 == 0, "exact pool grid");

// Scratch (__device__ globals = sanctioned scratch; zero-initialized at load).
// d_count is self-cleaned by pool_kernel each run -> invariant holds across replays.
__device__ int d_count[NRV];
__device__ __align__(16) int d_list[NRV * KMAX];   // 16B align for int4 loads

// ---------------------------------------------------------------------------
// Kernel 1: build + INTERLEAVED zero-fill.
// One guarded STG.128 of zeros per 4-ROI group (32 slots cover the ~23
// stores each thread owes). Between stores the warp runs ~30 instr of pure
// compute, so the store queue drains continuously and never throttles issue:
// the 56.6MB LTS drain hides under the ROI loop instead of serializing
// before it (the bulk-issue version measured fill+build = 20-22us serial).
// ---------------------------------------------------------------------------
__global__ __launch_bounds__(256) void build_fill_kernel(
    const float* __restrict__ rois, const float* __restrict__ pts,
    float* __restrict__ out)
{
    __shared__ float4 sA[N_ROIS];  // {cx, cy, r2_margin, cz}
    __shared__ float4 sB[N_ROIS];  // {cosa, sina, hdx, hdy}
    __shared__ float4 sC[N_ROIS];  // {hdz, vx, vy, vz}

    int t = threadIdx.x;
    int p = blockIdx.x * blockDim.x + t;      // always < N_PTS (exact grid)

    float px = pts[3 * p + 0];
    float py = pts[3 * p + 1];
    float pz = pts[3 * p + 2];

    if (t < N_ROIS) {
        const float* R = rois + t * 7;
        float cx = R[0], cy = R[1], cz = R[2];
        float dx = R[3], dy = R[4], dz = R[5];
        float ry = R[6];
        float hdx = dx * 0.5f, hdy = dy * 0.5f, hdz = dz * 0.5f;
        float r2  = (hdx * hdx + hdy * hdy) * 1.0002f + 1e-6f;  // conservative
        float ca  = cosf(-ry), sa = sinf(-ry);
        sA[t] = make_float4(cx, cy, r2, cz);
        sB[t] = make_float4(ca, sa, hdx, hdy);
        sC[t] = make_float4(hdz, dx / (float)OUTD, dy / (float)OUTD, dz / (float)OUTD);
    }
    __syncthreads();

    float4* o4 = (float4*)out;
    const float4 z = make_float4(0.f, 0.f, 0.f, 0.f);
    int fi = p;                                // fill cursor, stride N_PTS

    for (int rr = 0; rr < N_ROIS; rr += 4) {
        // One interleaved zero store per 4-ROI group (guarded; 32 groups
        // cover the <=23 stores this thread owes).
        if (fi < NF4) { __stcs(&o4[fi], z); fi += N_PTS; }

        #pragma unroll
        for (int u = 0; u < 4; u++) {
            int r = rr + u;
            float4 A = sA[r];                 // broadcast LDS.128 (uniform r)
            float sx = px - A.x;
            float sy = py - A.y;
            float d2 = sx * sx + sy * sy;
            if (d2 > A.z) continue;           // ~99.8% rejected here

            float sz = pz - A.w;
            float4 B = sB[r];
            float4 C = sC[r];
            float lx = sx * B.x - sy * B.y;   // rotate into roi frame (angle = -ry)
            float ly = sx * B.y + sy * B.x;
            bool in_box = (lx > -B.z) && (lx < B.z) &&
                          (ly > -B.w) && (ly < B.w) &&
                          (fabsf(sz - C.x) <= C.x);
            if (!in_box) continue;

            int xi = min(OUTD - 1, max(0, (int)floorf((lx + B.z) / C.y)));
            int yi = min(OUTD - 1, max(0, (int)floorf((ly + B.w) / C.z)));
            int zi = min(OUTD - 1, max(0, (int)floorf(sz / C.w)));
            int rv = r * N_VOX + xi * (OUTD * OUTD) + yi * OUTD + zi;
            int c = atomicAdd(&d_count[rv], 1);
            if (c < KMAX) d_list[rv * KMAX + c] = p;
        }
    }
    // Safety tail (never taken for this geometry: 23 <= 32 slots).
    for (; fi < NF4; fi += N_PTS) __stcs(&o4[fi], z);
}

// ---------------------------------------------------------------------------
// Kernel 2: gather pool — R5 exact form (best pool measurement). Block =
// 256 voxels, single wave. Coalesced count scan + self-clean, ballot-
// compaction of non-empty voxels, 2-deep pipeline over queue entries.
// Empty voxels: nothing (zeros already written by build's interleaved fill).
// ---------------------------------------------------------------------------
__global__ __launch_bounds__(256, 6) void pool_kernel(
    const float* __restrict__ rois, const float* __restrict__ pts,
    const float* __restrict__ feat, float* __restrict__ out)
{
    __shared__ int sCnt[256];
    __shared__ int sQ[256];
    __shared__ int sQn;

    int t    = threadIdx.x;
    int lane = t & 31;
    int wid  = t >> 5;
    int vblock = blockIdx.x << 8;             // first voxel of this block

    int c = d_count[vblock + t];              // coalesced 1KB burst
    sCnt[t] = c;
    if (c) d_count[vblock + t] = 0;           // self-clean only dirty entries
    if (t == 0) sQn = 0;
    __syncthreads();

    // Ballot-compact non-empty local voxel ids into sQ.
    unsigned m = __ballot_sync(0xffffffffu, c > 0);
    int base = 0;
    if (lane == 0 && m) base = atomicAdd(&sQn, __popc(m));
    base = __shfl_sync(0xffffffffu, base, 0);
    if (c > 0) sQ[base + __popc(m & ((1u << lane) - 1u))] = t;
    __syncthreads();
    int qn = sQn;

    // Warps grab entries strided; 2-deep pipeline hides list-load latency.
    int i = wid;
    int nGv = -1, nN = 0;
    int4 nP4 = make_int4(0, 0, 0, 0);
    if (i < qn) {
        int lv = sQ[i];
        nGv = vblock + lv;
        nN  = sCnt[lv];
        nP4 = *(const int4*)&d_list[(size_t)nGv * KMAX];
    }
    while (nGv >= 0) {
        int gv = nGv, n = nN;
        int4 p4 = nP4;
        i += 8;
        if (i < qn) {
            int lv = sQ[i];
            nGv = vblock + lv;
            nN  = sCnt[lv];
            nP4 = *(const int4*)&d_list[(size_t)nGv * KMAX];   // prefetch next
        } else {
            nGv = -1;
        }

        float mx0 = -FLT_MAX, mx1 = -FLT_MAX;
        int mm = min(n, KMAX);
        {   // up to 4 independent feature-row loads (MLP), predicated
            float2 v0, v1, v2, v3;
            if (mm > 0) v0 = ((const float2*)(feat + (size_t)p4.x * NCH))[lane];
            if (mm > 1) v1 = ((const float2*)(feat + (size_t)p4.y * NCH))[lane];
            if (mm > 2) v2 = ((const float2*)(feat + (size_t)p4.z * NCH))[lane];
            if (mm > 3) v3 = ((const float2*)(feat + (size_t)p4.w * NCH))[lane];
            if (mm > 0) { mx0 = fmaxf(mx0, v0.x); mx1 = fmaxf(mx1, v0.y); }
            if (mm > 1) { mx0 = fmaxf(mx0, v1.x); mx1 = fmaxf(mx1, v1.y); }
            if (mm > 2) { mx0 = fmaxf(mx0, v2.x); mx1 = fmaxf(mx1, v2.y); }
            if (mm > 3) { mx0 = fmaxf(mx0, v3.x); mx1 = fmaxf(mx1, v3.y); }
        }
        const int* lst = &d_list[(size_t)gv * KMAX];
        for (int j = 4; j < mm; j++) {        // rare (P(n>4) tiny)
            int pid = lst[j];
            float2 v = ((const float2*)(feat + (size_t)pid * NCH))[lane];
            mx0 = fmaxf(mx0, v.x);
            mx1 = fmaxf(mx1, v.y);
        }

        if (n > KMAX) {
            // Correctness fallback (statistically never taken): rescan all
            // points. n is warp-uniform so the whole warp enters together.
            int r = gv / N_VOX, vox = gv % N_VOX;
            int xi = vox / (OUTD * OUTD), yi = (vox / OUTD) % OUTD, zi = vox % OUTD;
            const float* R = rois + r * 7;
            float cx = R[0], cy = R[1], cz = R[2];
            float dx = R[3], dy = R[4], dz = R[5];
            float ry = R[6];
            float hdx = dx * 0.5f, hdy = dy * 0.5f, hdz = dz * 0.5f;
            float ca = cosf(-ry), sa = sinf(-ry);
            float vx = dx / (float)OUTD, vy = dy / (float)OUTD, vz = dz / (float)OUTD;
            for (int bb = 0; bb < N_PTS; bb += 32) {
                int pp = bb + lane;
                bool hit = false;
                {
                    float sx = pts[3 * pp + 0] - cx;
                    float sy = pts[3 * pp + 1] - cy;
                    float szz = pts[3 * pp + 2] - cz;
                    float lx = sx * ca - sy * sa;
                    float ly = sx * sa + sy * ca;
                    if ((lx > -hdx) && (lx < hdx) && (ly > -hdy) && (ly < hdy) &&
                        (fabsf(szz - hdz) <= hdz)) {
                        int xa = min(OUTD - 1, max(0, (int)floorf((lx + hdx) / vx)));
                        int ya = min(OUTD - 1, max(0, (int)floorf((ly + hdy) / vy)));
                        int za = min(OUTD - 1, max(0, (int)floorf(szz / vz)));
                        hit = (xa == xi) && (ya == yi) && (za == zi);
                    }
                }
                unsigned mk = __ballot_sync(0xffffffffu, hit);
                while (mk) {
                    int src = __ffs(mk) - 1;
                    mk &= mk - 1;
                    int pid = bb + src;
                    float2 v = ((const float2*)(feat + (size_t)pid * NCH))[lane];
                    mx0 = fmaxf(mx0, v.x);
                    mx1 = fmaxf(mx1, v.y);
                }
            }
        }

        float2* o = (float2*)(out + (size_t)gv * NCH);
        __stcs(&o[lane], make_float2(mx0, mx1));
    }
}

// ---------------------------------------------------------------------------
extern "C" void kernel_launch(void* const* d_in, const int* in_sizes, int n_in,
                              void* d_out, int out_size)
{
    const float* rois = (const float*)d_in[0];       // (128, 7)
    const float* pts  = (const float*)d_in[1];       // (160000, 3)
    const float* feat = (const float*)d_in[2];       // (160000, 64)
    float* out = (float*)d_out;                      // (128, 12, 12, 12, 64)

    build_fill_kernel<<<N_PTS / 256, 256>>>(rois, pts, out); // interleaved fill+build
    pool_kernel<<<NRV / 256, 256>>>(rois, pts, feat, out);   // scan pool (R5 form)
}